// round 3
// baseline (speedup 1.0000x reference)
#include <cuda_runtime.h>
#include <math.h>

#define BB   64
#define CC   3
#define HH_  32
#define WW_  32
#define HID  128
#define PRE  32
#define VMAX 256
#define IND  14
#define TT   2700              // (32-2)*(32-2)*3
#define MTOT (BB*TT)           // 172800
#define G3   (3*HID)           // 384

// Scratch (static device arrays: allocation-free at runtime)
__device__ float g_xg[(size_t)MTOT * G3];   // x-gates, includes b_ih
__device__ float g_hs[(size_t)MTOT * HID];  // hidden states

__device__ __forceinline__ float sigf(float x) { return 1.0f / (1.0f + __expf(-x)); }

// ---------------------------------------------------------------------------
// Kernel 1: img2input -> sigmoid(pre) -> xg = pre @ W_ih^T + b_ih
// Block = 32 rows, 384 threads (one per gate output). W_ih row in registers.
// ---------------------------------------------------------------------------
__global__ __launch_bounds__(384) void k_pre_xg(
    const float* __restrict__ x,
    const float* __restrict__ Wpre, const float* __restrict__ bpre,
    const float* __restrict__ Wih,  const float* __restrict__ bih)
{
    __shared__ __align__(16) float s_inp[32 * IND];
    __shared__ __align__(16) float s_pre[32 * PRE];

    const int tid = threadIdx.x;
    const int m0  = blockIdx.x * 32;

    // Phase A: build 32 x 14 input rows
    for (int e = tid; e < 32 * IND; e += 384) {
        int rr = e / IND, i = e % IND;
        int m = m0 + rr;
        int b = m / TT, t = m % TT;
        int c = t % CC; int pix = t / CC;
        int col = pix % (WW_ - 2); int row = pix / (WW_ - 2);
        float v;
        if (i < 12) {
            int grp = i / 3, ch = i % 3;
            int ri = row + (grp == 3 ? 1 : 0);
            int ci = col + (grp == 1 ? 1 : (grp == 2 ? 2 : 0));
            v = x[((size_t)(b * CC + ch) * HH_ + ri) * WW_ + ci];
        } else {
            int k = i - 12;
            v = (k < c) ? x[((size_t)(b * CC + k) * HH_ + row + 1) * WW_ + col + 1]
                        : -1.0f;
        }
        s_inp[rr * IND + i] = v;
    }
    __syncthreads();

    // Phase B: pre = sigmoid(inp @ Wpre^T + bpre)   (32 rows x 32)
    for (int e = tid; e < 32 * PRE; e += 384) {
        int rr = e >> 5, j = e & 31;
        float s = __ldg(&bpre[j]);
        #pragma unroll
        for (int i = 0; i < IND; i++)
            s += __ldg(&Wpre[j * IND + i]) * s_inp[rr * IND + i];
        s_pre[rr * PRE + j] = sigf(s);
    }
    __syncthreads();

    // Phase C: xg[rr][g] = bih[g] + sum_j Wih[g][j] * pre[rr][j]
    const int g = tid;
    float w[PRE];
    #pragma unroll
    for (int q = 0; q < PRE / 4; q++) {
        float4 v = ((const float4*)(Wih + (size_t)g * PRE))[q];
        w[4*q] = v.x; w[4*q+1] = v.y; w[4*q+2] = v.z; w[4*q+3] = v.w;
    }
    const float bg = __ldg(&bih[g]);
    for (int rr = 0; rr < 32; rr++) {
        const float4* p4 = (const float4*)(s_pre + rr * PRE);
        float a0 = 0.f, a1 = 0.f, a2 = 0.f, a3 = 0.f;
        #pragma unroll
        for (int q = 0; q < PRE / 4; q++) {
            float4 pv = p4[q];
            a0 += w[4*q]   * pv.x;
            a1 += w[4*q+1] * pv.y;
            a2 += w[4*q+2] * pv.z;
            a3 += w[4*q+3] * pv.w;
        }
        g_xg[(size_t)(m0 + rr) * G3 + g] = bg + ((a0 + a1) + (a2 + a3));
    }
}

// ---------------------------------------------------------------------------
// Kernel 2: sequential GRU scan. One block per batch element, 384 threads,
// thread g owns W_hh row g in registers. h lives in shared memory.
// ---------------------------------------------------------------------------
__global__ __launch_bounds__(384, 1) void k_gru(
    const float* __restrict__ Whh, const float* __restrict__ bhh)
{
    __shared__ __align__(16) float s_h[HID];
    __shared__ float s_ar[HID], s_az[HID], s_hn[HID], s_xn[HID];

    const int g = threadIdx.x;
    const int b = blockIdx.x;

    float w[HID];
    #pragma unroll
    for (int q = 0; q < HID / 4; q++) {
        float4 v = ((const float4*)(Whh + (size_t)g * HID))[q];
        w[4*q] = v.x; w[4*q+1] = v.y; w[4*q+2] = v.z; w[4*q+3] = v.w;
    }
    const float bg = __ldg(&bhh[g]);

    if (g < HID) s_h[g] = 0.0f;
    __syncthreads();

    const size_t base = (size_t)b * TT;
    float xcur = g_xg[base * G3 + g];

    for (int t = 0; t < TT; t++) {
        // prefetch next step's x-gate (hides DRAM latency under the dot)
        float xnext = 0.0f;
        if (t + 1 < TT) xnext = g_xg[(base + t + 1) * G3 + g];

        // hg = W_hh[g] . h  + b_hh[g]
        float a0 = 0.f, a1 = 0.f, a2 = 0.f, a3 = 0.f;
        const float4* h4 = (const float4*)s_h;
        #pragma unroll
        for (int q = 0; q < HID / 4; q++) {
            float4 hv = h4[q];
            a0 += w[4*q]   * hv.x;
            a1 += w[4*q+1] * hv.y;
            a2 += w[4*q+2] * hv.z;
            a3 += w[4*q+3] * hv.w;
        }
        float hg = bg + ((a0 + a1) + (a2 + a3));

        if (g < HID)            s_ar[g]          = xcur + hg;
        else if (g < 2 * HID)   s_az[g - HID]    = xcur + hg;
        else { s_hn[g - 2*HID] = hg; s_xn[g - 2*HID] = xcur; }
        __syncthreads();

        if (g < HID) {
            float r = sigf(s_ar[g]);
            float z = sigf(s_az[g]);
            float n = tanhf(s_xn[g] + r * s_hn[g]);
            float hp = s_h[g];
            float hnew = (1.0f - z) * n + z * hp;
            s_h[g] = hnew;
            g_hs[(base + t) * HID + g] = hnew;
        }
        __syncthreads();
        xcur = xnext;
    }
}

// ---------------------------------------------------------------------------
// Kernel 3: out = hs @ W_post^T + b_post, scattered into padded output.
// Block tile: 64 rows x 256 cols, 256 threads, 8x8 register micro-tiles.
// W_post transposed in smem with +1 pad (conflict-free); strided cols so
// both LDS reads and global stores are conflict-free / coalesced.
// ---------------------------------------------------------------------------
#define VP (VMAX + 1)  // 257 padded row stride for transposed W

__global__ __launch_bounds__(256) void k_post(
    const float* __restrict__ Wpost, const float* __restrict__ bpost,
    float* __restrict__ out)
{
    extern __shared__ float sm[];
    float* sWt = sm;                 // [HID][VP]
    float* sA  = sm + HID * VP;      // [64][HID]

    const int tid = threadIdx.x;
    const int m0  = blockIdx.x * 64;

    for (int e = tid; e < VMAX * HID; e += 256) {
        int v = e >> 7, k = e & (HID - 1);
        sWt[k * VP + v] = Wpost[e];
    }
    for (int e = tid; e < 64 * HID; e += 256) {
        sA[e] = g_hs[(size_t)m0 * HID + e];
    }
    __syncthreads();

    const int tx = tid & 31;   // column lane: cols tx + 32*j
    const int ty = tid >> 5;   // row lane:    rows ty + 8*i

    float acc[8][8];
    #pragma unroll
    for (int i = 0; i < 8; i++)
        #pragma unroll
        for (int j = 0; j < 8; j++) acc[i][j] = 0.0f;

    #pragma unroll 2
    for (int k = 0; k < HID; k++) {
        float a[8], bb[8];
        #pragma unroll
        for (int i = 0; i < 8; i++) a[i] = sA[(ty + 8 * i) * HID + k];  // broadcast
        #pragma unroll
        for (int j = 0; j < 8; j++) bb[j] = sWt[k * VP + tx + 32 * j];  // conflict-free
        #pragma unroll
        for (int i = 0; i < 8; i++)
            #pragma unroll
            for (int j = 0; j < 8; j++)
                acc[i][j] += a[i] * bb[j];
    }

    #pragma unroll
    for (int i = 0; i < 8; i++) {
        int m = m0 + ty + 8 * i;
        int b = m / TT, t = m % TT;
        int c = t % CC; int pix = t / CC;
        int col = pix % (WW_ - 2); int row = pix / (WW_ - 2);
        size_t obase = (((size_t)(b * CC + c) * HH_ + (row + 1)) * WW_ + (col + 1)) * (size_t)VMAX;
        #pragma unroll
        for (int j = 0; j < 8; j++) {
            int v = tx + 32 * j;
            out[obase + v] = acc[i][j] + __ldg(&bpost[v]);
        }
    }
}

// ---------------------------------------------------------------------------
extern "C" void kernel_launch(void* const* d_in, const int* in_sizes, int n_in,
                              void* d_out, int out_size)
{
    const float* x     = (const float*)d_in[0];
    const float* Wpre  = (const float*)d_in[1];
    const float* bpre  = (const float*)d_in[2];
    const float* Wih   = (const float*)d_in[3];
    const float* bih   = (const float*)d_in[4];
    const float* Whh   = (const float*)d_in[5];
    const float* bhh   = (const float*)d_in[6];
    const float* Wpost = (const float*)d_in[7];
    const float* bpost = (const float*)d_in[8];
    float* out = (float*)d_out;

    // zero padded output (pad ring must be 0; buffer is poisoned)
    cudaMemsetAsync(out, 0, (size_t)out_size * sizeof(float), 0);

    // Phase 1: x-gates
    k_pre_xg<<<MTOT / 32, 384>>>(x, Wpre, bpre, Wih, bih);

    // Phase 2: sequential GRU (one CTA per batch element)
    k_gru<<<BB, 384>>>(Whh, bhh);

    // Phase 3: post projection + scatter
    const int smem3 = (HID * VP + 64 * HID) * (int)sizeof(float);  // ~164 KB
    static int s_attr_set = 0;
    if (!s_attr_set) {
        cudaFuncSetAttribute(k_post, cudaFuncAttributeMaxDynamicSharedMemorySize, smem3);
        s_attr_set = 1;
    }
    k_post<<<MTOT / 64, 256, smem3>>>(Wpost, bpost, out);
}

// round 4
// speedup vs baseline: 1.1475x; 1.1475x over previous
#include <cuda_runtime.h>
#include <math.h>

#define BB   64
#define CC   3
#define HH_  32
#define WW_  32
#define HID  128
#define PRE  32
#define VMAX 256
#define IND  14
#define TT   2700              // (32-2)*(32-2)*3
#define MTOT (BB*TT)           // 172800
#define G3   (3*HID)           // 384

typedef unsigned long long ull;

// Scratch (static device arrays: allocation-free at runtime)
__device__ float g_xg[(size_t)MTOT * G3];   // x-gates, includes b_ih
__device__ float g_hs[(size_t)MTOT * HID];  // hidden states

__device__ __forceinline__ float sigf(float x) {
    return __fdividef(1.0f, 1.0f + __expf(-x));
}
__device__ __forceinline__ float tanhf_fast(float x) {
    return __fdividef(2.0f, 1.0f + __expf(-2.0f * x)) - 1.0f;
}

// Packed 2-wide fp32 FMA (sm_100+): d = a*b + c on {lo,hi} pairs
__device__ __forceinline__ ull ffma2(ull a, ull b, ull c) {
    ull d;
    asm("fma.rn.f32x2 %0, %1, %2, %3;" : "=l"(d) : "l"(a), "l"(b), "l"(c));
    return d;
}
__device__ __forceinline__ float2 unpack2(ull u) {
    float2 f;
    asm("mov.b64 {%0, %1}, %2;" : "=f"(f.x), "=f"(f.y) : "l"(u));
    return f;
}
__device__ __forceinline__ ull pack2(float lo, float hi) {
    ull u;
    asm("mov.b64 %0, {%1, %2};" : "=l"(u) : "f"(lo), "f"(hi));
    return u;
}

// ---------------------------------------------------------------------------
// Kernel 1: img2input -> sigmoid(pre) -> xg = pre @ W_ih^T + b_ih
// Block = 32 rows, 384 threads (one per gate output). W_ih row in registers.
// ---------------------------------------------------------------------------
__global__ __launch_bounds__(384) void k_pre_xg(
    const float* __restrict__ x,
    const float* __restrict__ Wpre, const float* __restrict__ bpre,
    const float* __restrict__ Wih,  const float* __restrict__ bih)
{
    __shared__ __align__(16) float s_inp[32 * IND];
    __shared__ __align__(16) float s_pre[32 * PRE];

    const int tid = threadIdx.x;
    const int m0  = blockIdx.x * 32;

    // Phase A: build 32 x 14 input rows
    for (int e = tid; e < 32 * IND; e += 384) {
        int rr = e / IND, i = e % IND;
        int m = m0 + rr;
        int b = m / TT, t = m % TT;
        int c = t % CC; int pix = t / CC;
        int col = pix % (WW_ - 2); int row = pix / (WW_ - 2);
        float v;
        if (i < 12) {
            int grp = i / 3, ch = i % 3;
            int ri = row + (grp == 3 ? 1 : 0);
            int ci = col + (grp == 1 ? 1 : (grp == 2 ? 2 : 0));
            v = x[((size_t)(b * CC + ch) * HH_ + ri) * WW_ + ci];
        } else {
            int k = i - 12;
            v = (k < c) ? x[((size_t)(b * CC + k) * HH_ + row + 1) * WW_ + col + 1]
                        : -1.0f;
        }
        s_inp[rr * IND + i] = v;
    }
    __syncthreads();

    // Phase B: pre = sigmoid(inp @ Wpre^T + bpre)   (32 rows x 32)
    for (int e = tid; e < 32 * PRE; e += 384) {
        int rr = e >> 5, j = e & 31;
        float s = __ldg(&bpre[j]);
        #pragma unroll
        for (int i = 0; i < IND; i++)
            s += __ldg(&Wpre[j * IND + i]) * s_inp[rr * IND + i];
        s_pre[rr * PRE + j] = sigf(s);
    }
    __syncthreads();

    // Phase C: xg[rr][g] = bih[g] + sum_j Wih[g][j] * pre[rr][j]  (packed f32x2)
    const int g = tid;
    ull w2[PRE / 2];
    const ulonglong2* wp = (const ulonglong2*)(Wih + (size_t)g * PRE);
    #pragma unroll
    for (int q = 0; q < PRE / 4; q++) {
        ulonglong2 v = wp[q];
        w2[2 * q] = v.x; w2[2 * q + 1] = v.y;
    }
    const float bg = __ldg(&bih[g]);
    for (int rr = 0; rr < 32; rr++) {
        const ulonglong2* p2 = (const ulonglong2*)(s_pre + rr * PRE);
        ull a0 = 0ull, a1 = 0ull;
        #pragma unroll
        for (int q = 0; q < PRE / 4; q++) {
            ulonglong2 pv = p2[q];
            a0 = ffma2(w2[2 * q],     pv.x, a0);
            a1 = ffma2(w2[2 * q + 1], pv.y, a1);
        }
        float2 f0 = unpack2(a0), f1 = unpack2(a1);
        g_xg[(size_t)(m0 + rr) * G3 + g] = bg + ((f0.x + f0.y) + (f1.x + f1.y));
    }
}

// ---------------------------------------------------------------------------
// Kernel 2: sequential GRU scan. One block per batch element, 384 threads,
// thread g owns W_hh row g as 64 packed f32x2 registers. h in shared memory.
// Dot uses fma.rn.f32x2 (2 FMAs/instr); tail uses MUFU-based fast sigmoid/tanh.
// ---------------------------------------------------------------------------
__global__ __launch_bounds__(384, 1) void k_gru(
    const float* __restrict__ Whh, const float* __restrict__ bhh)
{
    __shared__ __align__(16) float s_h[HID];
    __shared__ float s_ar[HID], s_az[HID], s_hn[HID], s_xn[HID];

    const int g = threadIdx.x;
    const int b = blockIdx.x;

    // W_hh row g in packed registers: 64 x f32x2 = 128 regs
    ull w2[HID / 2];
    const ulonglong2* wp = (const ulonglong2*)(Whh + (size_t)g * HID);
    #pragma unroll
    for (int q = 0; q < HID / 4; q++) {
        ulonglong2 v = wp[q];
        w2[2 * q] = v.x; w2[2 * q + 1] = v.y;
    }
    const float bg = __ldg(&bhh[g]);

    if (g < HID) s_h[g] = 0.0f;
    __syncthreads();

    const size_t base = (size_t)b * TT;
    const float* xgp = g_xg + base * G3 + g;

    // 2-deep x-gate prefetch pipeline (covers DRAM latency ~2 steps)
    float xcur = xgp[0];
    float xn1  = xgp[G3];

    for (int t = 0; t < TT; t++) {
        float xn2 = 0.0f;
        if (t + 2 < TT) xn2 = xgp[(size_t)(t + 2) * G3];

        // hg = W_hh[g] . h + b_hh[g]   (packed: 32 FFMA2 over 2 chains)
        ull a0 = 0ull, a1 = 0ull;
        const ulonglong2* h2 = (const ulonglong2*)s_h;
        #pragma unroll
        for (int q = 0; q < HID / 4; q++) {
            ulonglong2 hv = h2[q];           // LDS.128 broadcast
            a0 = ffma2(w2[2 * q],     hv.x, a0);
            a1 = ffma2(w2[2 * q + 1], hv.y, a1);
        }
        float2 f0 = unpack2(a0), f1 = unpack2(a1);
        float hg = bg + ((f0.x + f0.y) + (f1.x + f1.y));

        if (g < HID)            s_ar[g]          = xcur + hg;
        else if (g < 2 * HID)   s_az[g - HID]    = xcur + hg;
        else { s_hn[g - 2*HID] = hg; s_xn[g - 2*HID] = xcur; }
        __syncthreads();

        if (g < HID) {
            float r = sigf(s_ar[g]);
            float z = sigf(s_az[g]);
            float n = tanhf_fast(s_xn[g] + r * s_hn[g]);
            float hp = s_h[g];
            float hnew = fmaf(z, hp - n, n);   // (1-z)*n + z*h
            s_h[g] = hnew;
            g_hs[(base + t) * HID + g] = hnew;
        }
        __syncthreads();
        xcur = xn1; xn1 = xn2;
    }
}

// ---------------------------------------------------------------------------
// Kernel 3: out = hs @ W_post^T + b_post, scattered into padded output.
// Block tile: 64 rows x 256 cols, 256 threads, 8x8 register micro-tiles,
// packed f32x2 math. Columns paired adjacently so B reads are LDS.64 and
// stores are STG.64 coalesced. W_post transposed in smem, VP=258 keeps
// 8-byte alignment per k-row and conflict-freedom.
// ---------------------------------------------------------------------------
#define VP (VMAX + 2)  // 258: even padded row stride (8B-aligned pairs)

__global__ __launch_bounds__(256) void k_post(
    const float* __restrict__ Wpost, const float* __restrict__ bpost,
    float* __restrict__ out)
{
    extern __shared__ float sm[];
    float* sWt = sm;                 // [HID][VP]  transposed W_post
    float* sA  = sm + HID * VP;      // [64][HID]

    const int tid = threadIdx.x;
    const int m0  = blockIdx.x * 64;

    for (int e = tid; e < VMAX * HID; e += 256) {
        int v = e >> 7, k = e & (HID - 1);
        sWt[k * VP + v] = Wpost[e];
    }
    for (int e = tid; e < 64 * HID; e += 256) {
        sA[e] = g_hs[(size_t)m0 * HID + e];
    }
    __syncthreads();

    const int tx = tid & 31;   // column pair lane: cols 64*j + 2*tx + {0,1}
    const int ty = tid >> 5;   // row lane:         rows ty + 8*i

    ull acc[8][4];
    #pragma unroll
    for (int i = 0; i < 8; i++)
        #pragma unroll
        for (int j = 0; j < 4; j++) acc[i][j] = 0ull;

    #pragma unroll 2
    for (int k = 0; k < HID; k++) {
        ull ap[8];
        #pragma unroll
        for (int i = 0; i < 8; i++) {
            float a = sA[(ty + 8 * i) * HID + k];     // broadcast LDS
            ap[i] = pack2(a, a);
        }
        ull bb[4];
        #pragma unroll
        for (int j = 0; j < 4; j++)
            bb[j] = *(const ull*)&sWt[k * VP + 64 * j + 2 * tx];  // LDS.64, conflict-free
        #pragma unroll
        for (int i = 0; i < 8; i++)
            #pragma unroll
            for (int j = 0; j < 4; j++)
                acc[i][j] = ffma2(ap[i], bb[j], acc[i][j]);
    }

    #pragma unroll
    for (int i = 0; i < 8; i++) {
        int m = m0 + ty + 8 * i;
        int b = m / TT, t = m % TT;
        int c = t % CC; int pix = t / CC;
        int col = pix % (WW_ - 2); int row = pix / (WW_ - 2);
        size_t obase = (((size_t)(b * CC + c) * HH_ + (row + 1)) * WW_ + (col + 1)) * (size_t)VMAX;
        #pragma unroll
        for (int j = 0; j < 4; j++) {
            int v = 64 * j + 2 * tx;
            float2 r = unpack2(acc[i][j]);
            float2 o;
            o.x = r.x + __ldg(&bpost[v]);
            o.y = r.y + __ldg(&bpost[v + 1]);
            *(float2*)&out[obase + v] = o;   // STG.64, coalesced per warp
        }
    }
}

// ---------------------------------------------------------------------------
extern "C" void kernel_launch(void* const* d_in, const int* in_sizes, int n_in,
                              void* d_out, int out_size)
{
    const float* x     = (const float*)d_in[0];
    const float* Wpre  = (const float*)d_in[1];
    const float* bpre  = (const float*)d_in[2];
    const float* Wih   = (const float*)d_in[3];
    const float* bih   = (const float*)d_in[4];
    const float* Whh   = (const float*)d_in[5];
    const float* bhh   = (const float*)d_in[6];
    const float* Wpost = (const float*)d_in[7];
    const float* bpost = (const float*)d_in[8];
    float* out = (float*)d_out;

    // zero padded output (pad ring must be 0; buffer is poisoned)
    cudaMemsetAsync(out, 0, (size_t)out_size * sizeof(float), 0);

    // Phase 1: x-gates
    k_pre_xg<<<MTOT / 32, 384>>>(x, Wpre, bpre, Wih, bih);

    // Phase 2: sequential GRU (one CTA per batch element)
    k_gru<<<BB, 384>>>(Whh, bhh);

    // Phase 3: post projection + scatter
    const int smem3 = (HID * VP + 64 * HID) * (int)sizeof(float);  // ~165 KB
    static int s_attr_set = 0;
    if (!s_attr_set) {
        cudaFuncSetAttribute(k_post, cudaFuncAttributeMaxDynamicSharedMemorySize, smem3);
        s_attr_set = 1;
    }
    k_post<<<MTOT / 64, 256, smem3>>>(Wpost, bpost, out);
}